// round 15
// baseline (speedup 1.0000x reference)
#include <cuda_runtime.h>

#define B_TOTAL 16384
#define NSTEPS  196

// Scratch (allocation-free: __device__ globals)
__device__ float g_xT[784 * B_TOTAL];    // transposed, PRE-HALVED input: [pixel][batch]
__device__ float g_w1T[NSTEPS * 4 * 20]; // fc1 weights: [(s*4+w)*20 + o]

// ---------------------------------------------------------------------------
// Prep kernel: float4 transpose of x -> g_xT = 0.5*x^T, plus fc1_w relayout.
// ---------------------------------------------------------------------------
__global__ void prep_kernel(const float* __restrict__ x, const float* __restrict__ fc1_w) {
    if (blockIdx.y == 25) {
        int t = threadIdx.y * 8 + threadIdx.x;
        int idx = blockIdx.x * 256 + t;
        if (idx < 784 * 20) {
            int p = idx / 20, o = idx % 20;
            g_w1T[idx] = fc1_w[o * 784 + p];
        }
        return;
    }
    __shared__ float tile[32][33];
    const int bBase = blockIdx.x * 32;
    const int pBase = blockIdx.y * 32;
    const int tx = threadIdx.x, ty = threadIdx.y;
    int p0 = pBase + tx * 4;
    float4 v = make_float4(0.f, 0.f, 0.f, 0.f);
    if (p0 < 784) v = *(const float4*)(x + (bBase + ty) * 784 + p0);
    tile[tx * 4 + 0][ty] = 0.5f * v.x;
    tile[tx * 4 + 1][ty] = 0.5f * v.y;
    tile[tx * 4 + 2][ty] = 0.5f * v.z;
    tile[tx * 4 + 3][ty] = 0.5f * v.w;
    __syncthreads();
    int p = pBase + ty;
    if (p < 784) {
        float4 w = make_float4(tile[ty][tx * 4 + 0], tile[ty][tx * 4 + 1],
                               tile[ty][tx * 4 + 2], tile[ty][tx * 4 + 3]);
        *(float4*)(g_xT + p * B_TOTAL + bBase + tx * 4) = w;
    }
}

// ---------------------------------------------------------------------------
// Apply U = [[u, v],[conj(v), -conj(u)]] on wire with stride S (16 amps).
// ---------------------------------------------------------------------------
template<int S>
__device__ __forceinline__ void applyUV(float* Sr, float* Si,
    float ur, float ui, float vr, float vi)
{
    #pragma unroll
    for (int g = 0; g < 8; g++) {
        int i0 = ((g & ~(S - 1)) << 1) | (g & (S - 1));
        int i1 = i0 + S;
        float x0r = Sr[i0], x0i = Si[i0], x1r = Sr[i1], x1i = Si[i1];
        Sr[i0] = ur * x0r - ui * x0i + vr * x1r - vi * x1i;
        Si[i0] = ur * x0i + ui * x0r + vr * x1i + vi * x1r;
        Sr[i1] = vr * x0r + vi * x0i - ur * x1r - ui * x1i;
        Si[i1] = vr * x0i - vi * x0r - ur * x1i + ui * x1r;
    }
}

template<int S>
__device__ __forceinline__ float xdot(const float* Sr, const float* Si) {
    float ar = 0.f, ai = 0.f;
    #pragma unroll
    for (int g = 0; g < 8; g++) {
        int i0 = ((g & ~(S - 1)) << 1) | (g & (S - 1));
        int i1 = i0 + S;
        ar += Sr[i0] * Sr[i1];
        ai += Si[i0] * Si[i1];
    }
    return ar + ai;
}

// Quaternion chain: RZ(a4)RY(a3)RZ(a2)RY(a1)RZ(a0) * G, G=[gA,gB;gB,-gA].
__device__ __forceinline__ void chain5(const float* a, float gA, float gB,
    float& ur, float& ui, float& vr, float& vi)
{
    float c0a = __cosf(a[0]), s0a = __sinf(a[0]);
    float c1a = __cosf(a[1]), s1a = __sinf(a[1]);
    float c2a = __cosf(a[2]), s2a = __sinf(a[2]);
    float c3a = __cosf(a[3]), s3a = __sinf(a[3]);
    float c4a = __cosf(a[4]), s4a = __sinf(a[4]);
    float qw = c4a * c3a, qx = -s4a * s3a, qy = c4a * s3a, qz = s4a * c3a;
    float tw = qw * c2a - qz * s2a;
    float tx = qx * c2a + qy * s2a;
    float ty = qy * c2a - qx * s2a;
    float tz = qz * c2a + qw * s2a;
    qw = tw * c1a - ty * s1a;
    qx = tx * c1a - tz * s1a;
    qy = ty * c1a + tw * s1a;
    qz = tz * c1a + tx * s1a;
    tw = qw * c0a - qz * s0a;
    tx = qx * c0a + qy * s0a;
    ty = qy * c0a - qx * s0a;
    tz = qz * c0a + qw * s0a;
    ur = tw * gA - ty * gB;
    ui = -(tz * gA + tx * gB);
    vr = tw * gB + ty * gA;
    vi = tx * gA - tz * gB;
}

// Angle loader: 16 (pre-halved) angles of window (i2,j2), edge-masked.
__device__ __forceinline__ void loadA(float* A, int i2, int j2, bool valid, int e) {
    int hh = (i2 == 26) ? 2 : 4;
    int ww = (j2 == 26) ? 2 : 4;
    int hw = hh * ww;
    int base = i2 * 28 + j2;
    #pragma unroll
    for (int k = 0; k < 16; k++) {
        float v = 0.f;
        if (valid && k < hw) {
            int r, c;
            if (ww == 4) { r = k >> 2; c = k & 3; }
            else         { r = k >> 1; c = k & 1; }
            v = g_xT[(base + r * 28 + c) * B_TOTAL + e];
        }
        A[k] = v;
    }
}

// ---------------------------------------------------------------------------
// Main kernel: warp-specialized. Warps 0-3 = STATE (applies+CRZ),
// warps 4-7 = OBS (gate build, observables, fc1). Pair (w, w+4) shares an
// SMSP (wid%4) and the same 32 elements. One __syncthreads per step,
// double-buffered smem, obs lags state by one step.
// ---------------------------------------------------------------------------
__global__ __launch_bounds__(256, 1) void quanv_kernel(
    const float* __restrict__ crz_p, const float* __restrict__ ry_p,
    const float* __restrict__ fc1_b, const float* __restrict__ fc2_w,
    const float* __restrict__ fc2_b, float* __restrict__ out)
{
    __shared__ float2 sbuf[2][16][128];   // post-CRZ state  [buf][amp][elem]
    __shared__ float4 gbuf[2][4][128];    // gates (u,v)     [buf][wire][elem]

    const int lane = threadIdx.x & 31;
    const int wid  = threadIdx.x >> 5;
    const int role = wid >> 2;            // 0 = state, 1 = obs
    const int sw   = wid & 3;
    const int e    = blockIdx.x * 128 + sw * 32 + lane;
    const float RS = 0.7071067811865476f;

    // CRZ phases (state warp uses; cheap for all)
    const float th = __ldg(crz_p);
    const float c1 = __cosf(0.5f * th), s1 = __sinf(0.5f * th);
    const float c2 = __cosf(th),        s2 = __sinf(th);
    const float c4 = __cosf(2.0f * th), s4 = __sinf(2.0f * th);

    const float ryt = __ldg(ry_p);
    const float cTH  = __cosf(ryt);
    const float s2TH = 2.0f * __sinf(ryt);
    const float chh = __cosf(0.5f * ryt), shh = __sinf(0.5f * ryt);
    const float gAf = RS * (chh + shh), gBf = RS * (chh - shh);

    // ---- per-role persistent registers ----
    float Sr[16], Si[16];                 // state warp
    float h1[20];                         // obs warp
    float Ahold[16];                      // obs: angles for step k+1
    int wi2 = 0, wj2 = 2;                 // obs: window coords for t = k+2

    if (role == 0) {
        #pragma unroll
        for (int n = 0; n < 16; n++) { Sr[n] = 0.f; Si[n] = 0.f; }
        Sr[0] = 1.f;
    } else {
        #pragma unroll
        for (int o = 0; o < 20; o++) h1[o] = __ldg(&fc1_b[o]);
        // build gates(0) with G = H
        float A0[16];
        loadA(A0, 0, 0, true, e);
        float ur, ui, vr, vi;
        #pragma unroll
        for (int w = 0; w < 3; w++) {
            chain5(A0 + 5 * w, RS, RS, ur, ui, vr, vi);
            gbuf[0][w][sw * 32 + lane] = make_float4(ur, ui, vr, vi);
        }
        {
            float c0a = __cosf(A0[15]), s0a = __sinf(A0[15]);
            gbuf[0][3][sw * 32 + lane] =
                make_float4(c0a * RS, -s0a * RS, c0a * RS, -s0a * RS);
        }
        // angles for step 1
        loadA(Ahold, 0, 2, true, e);
    }

    const int le = sw * 32 + lane;

    #pragma unroll 1
    for (int k = 0; k <= NSTEPS; k++) {
        __syncthreads();
        if (role == 0) {
            if (k < NSTEPS) {
                float4 g0 = gbuf[k & 1][0][le];
                float4 g1 = gbuf[k & 1][1][le];
                float4 g2 = gbuf[k & 1][2][le];
                float4 g3 = gbuf[k & 1][3][le];
                applyUV<8>(Sr, Si, g0.x, g0.y, g0.z, g0.w);
                applyUV<4>(Sr, Si, g1.x, g1.y, g1.z, g1.w);
                applyUV<2>(Sr, Si, g2.x, g2.y, g2.z, g2.w);
                applyUV<1>(Sr, Si, g3.x, g3.y, g3.z, g3.w);
                // CRZ diagonal: sgn {0,-1,-1,0,-1,-2,0,1,-1,0,-2,1,0,1,1,4}
                #define CRZM(n, CR, CI) { float r_ = Sr[n]*(CR) - Si[n]*(CI); \
                                          Si[n]    = Sr[n]*(CI) + Si[n]*(CR); Sr[n] = r_; }
                CRZM(1,  c1, -s1)  CRZM(2,  c1, -s1)  CRZM(4,  c1, -s1)
                CRZM(5,  c2, -s2)  CRZM(7,  c1,  s1)  CRZM(8,  c1, -s1)
                CRZM(10, c2, -s2)  CRZM(11, c1,  s1)  CRZM(13, c1,  s1)
                CRZM(14, c1,  s1)  CRZM(15, c4,  s4)
                #undef CRZM
                #pragma unroll
                for (int m = 0; m < 16; m++)
                    sbuf[k & 1][m][le] = make_float2(Sr[m], Si[m]);
            }
        } else {
            // ---- build gates for step k+1 (G = H*Ry always, since k+1>=1) ----
            if (k < NSTEPS - 1) {
                float ur, ui, vr, vi;
                #pragma unroll
                for (int w = 0; w < 3; w++) {
                    chain5(Ahold + 5 * w, gAf, gBf, ur, ui, vr, vi);
                    gbuf[(k + 1) & 1][w][le] = make_float4(ur, ui, vr, vi);
                }
                float c0a = __cosf(Ahold[15]), s0a = __sinf(Ahold[15]);
                gbuf[(k + 1) & 1][3][le] =
                    make_float4(c0a * gAf, -s0a * gAf, c0a * gBf, -s0a * gBf);
            }
            // ---- prefetch angles for step k+2 ----
            float Anext[16];
            loadA(Anext, 2 * wi2, 2 * wj2, (k + 2) < NSTEPS, e);

            // ---- observables for step k-1 ----
            if (k >= 1) {
                float Tr[16], Ti[16];
                #pragma unroll
                for (int m = 0; m < 16; m++) {
                    float2 v = sbuf[(k - 1) & 1][m][le];
                    Tr[m] = v.x; Ti[m] = v.y;
                }
                float p[16];
                #pragma unroll
                for (int n = 0; n < 16; n++) p[n] = Tr[n] * Tr[n] + Ti[n] * Ti[n];
                float t8[8], z3 = 0.f;
                #pragma unroll
                for (int g = 0; g < 8; g++) { t8[g] = p[2*g] + p[2*g+1]; z3 += p[2*g] - p[2*g+1]; }
                float t4[4], z2 = 0.f;
                #pragma unroll
                for (int g = 0; g < 4; g++) { t4[g] = t8[2*g] + t8[2*g+1]; z2 += t8[2*g] - t8[2*g+1]; }
                float t2[2], z1 = 0.f;
                #pragma unroll
                for (int g = 0; g < 2; g++) { t2[g] = t4[2*g] + t4[2*g+1]; z1 += t4[2*g] - t4[2*g+1]; }
                float z0 = t2[0] - t2[1];

                float x0 = xdot<8>(Tr, Ti), x1 = xdot<4>(Tr, Ti);
                float x2 = xdot<2>(Tr, Ti), x3 = xdot<1>(Tr, Ti);
                float ev[4];
                ev[0] = cTH * z0 - s2TH * x0;
                ev[1] = cTH * z1 - s2TH * x1;
                ev[2] = cTH * z2 - s2TH * x2;
                ev[3] = cTH * z3 - s2TH * x3;

                const float4* w4 = (const float4*)(g_w1T + (k - 1) * 80);
                #pragma unroll
                for (int w = 0; w < 4; w++) {
                    #pragma unroll
                    for (int q = 0; q < 5; q++) {
                        float4 ww = __ldg(&w4[w * 5 + q]);
                        h1[q * 4 + 0] += ev[w] * ww.x;
                        h1[q * 4 + 1] += ev[w] * ww.y;
                        h1[q * 4 + 2] += ev[w] * ww.z;
                        h1[q * 4 + 3] += ev[w] * ww.w;
                    }
                }
            }
            #pragma unroll
            for (int m = 0; m < 16; m++) Ahold[m] = Anext[m];
            wj2++; if (wj2 == 14) { wj2 = 0; wi2++; }
        }
    }

    if (role == 1) {
        float o0 = __ldg(&fc2_b[0]), o1 = __ldg(&fc2_b[1]);
        #pragma unroll
        for (int o = 0; o < 20; o++) {
            float hv = h1[o];
            hv = (hv > 0.f) ? hv : 0.1f * hv;
            o0 += hv * __ldg(&fc2_w[o]);
            o1 += hv * __ldg(&fc2_w[20 + o]);
        }
        out[e * 2 + 0] = o0;
        out[e * 2 + 1] = o1;
    }
}

// ---------------------------------------------------------------------------
// Launch
// ---------------------------------------------------------------------------
extern "C" void kernel_launch(void* const* d_in, const int* in_sizes, int n_in,
                              void* d_out, int out_size) {
    const float* x      = (const float*)d_in[0];
    const float* crz_t  = (const float*)d_in[1];
    const float* ry_t   = (const float*)d_in[2];
    const float* fc1_w  = (const float*)d_in[3];
    const float* fc1_b  = (const float*)d_in[4];
    const float* fc2_w  = (const float*)d_in[5];
    const float* fc2_b  = (const float*)d_in[6];
    float* out = (float*)d_out;

    dim3 tbP(8, 32);
    dim3 tgP(B_TOTAL / 32, 26);
    prep_kernel<<<tgP, tbP>>>(x, fc1_w);

    // 128 elements/block (4 state warps + 4 obs warps), 128 blocks
    quanv_kernel<<<B_TOTAL / 128, 256>>>(crz_t, ry_t, fc1_b, fc2_w, fc2_b, out);
}

// round 16
// speedup vs baseline: 1.1225x; 1.1225x over previous
#include <cuda_runtime.h>

#define B_TOTAL 16384
#define NSTEPS  196

// Scratch (allocation-free: __device__ globals)
__device__ float g_xT[784 * B_TOTAL];    // transposed, PRE-HALVED input: [pixel][batch]
__device__ float g_w1T[NSTEPS * 4 * 20]; // fc1 weights: [(s*4+w)*20 + o]

// ---------------------------------------------------------------------------
// Prep kernel: float4 transpose of x -> g_xT = 0.5*x^T, plus fc1_w relayout.
// ---------------------------------------------------------------------------
__global__ void prep_kernel(const float* __restrict__ x, const float* __restrict__ fc1_w) {
    if (blockIdx.y == 25) {
        int t = threadIdx.y * 8 + threadIdx.x;
        int idx = blockIdx.x * 256 + t;
        if (idx < 784 * 20) {
            int p = idx / 20, o = idx % 20;
            g_w1T[idx] = fc1_w[o * 784 + p];
        }
        return;
    }
    __shared__ float tile[32][33];
    const int bBase = blockIdx.x * 32;
    const int pBase = blockIdx.y * 32;
    const int tx = threadIdx.x, ty = threadIdx.y;
    int p0 = pBase + tx * 4;
    float4 v = make_float4(0.f, 0.f, 0.f, 0.f);
    if (p0 < 784) v = *(const float4*)(x + (bBase + ty) * 784 + p0);
    tile[tx * 4 + 0][ty] = 0.5f * v.x;
    tile[tx * 4 + 1][ty] = 0.5f * v.y;
    tile[tx * 4 + 2][ty] = 0.5f * v.z;
    tile[tx * 4 + 3][ty] = 0.5f * v.w;
    __syncthreads();
    int p = pBase + ty;
    if (p < 784) {
        float4 w = make_float4(tile[ty][tx * 4 + 0], tile[ty][tx * 4 + 1],
                               tile[ty][tx * 4 + 2], tile[ty][tx * 4 + 3]);
        *(float4*)(g_xT + p * B_TOTAL + bBase + tx * 4) = w;
    }
}

// ---------------------------------------------------------------------------
// Apply U = [[u, v],[conj(v), -conj(u)]] on wire with stride S (16 amps).
// ---------------------------------------------------------------------------
template<int S>
__device__ __forceinline__ void applyUV(float* Sr, float* Si,
    float ur, float ui, float vr, float vi)
{
    #pragma unroll
    for (int g = 0; g < 8; g++) {
        int i0 = ((g & ~(S - 1)) << 1) | (g & (S - 1));
        int i1 = i0 + S;
        float x0r = Sr[i0], x0i = Si[i0], x1r = Sr[i1], x1i = Si[i1];
        Sr[i0] = ur * x0r - ui * x0i + vr * x1r - vi * x1i;
        Si[i0] = ur * x0i + ui * x0r + vr * x1i + vi * x1r;
        Sr[i1] = vr * x0r + vi * x0i - ur * x1r - ui * x1i;
        Si[i1] = vr * x0i - vi * x0r - ur * x1i + ui * x1r;
    }
}

template<int S>
__device__ __forceinline__ float xdot(const float* Sr, const float* Si) {
    float ar = 0.f, ai = 0.f;
    #pragma unroll
    for (int g = 0; g < 8; g++) {
        int i0 = ((g & ~(S - 1)) << 1) | (g & (S - 1));
        int i1 = i0 + S;
        ar += Sr[i0] * Sr[i1];
        ai += Si[i0] * Si[i1];
    }
    return ar + ai;
}

// Quaternion chain: RZ(a4)RY(a3)RZ(a2)RY(a1)RZ(a0) * G, G=[gA,gB;gB,-gA].
__device__ __forceinline__ void chain5(const float* a, float gA, float gB,
    float& ur, float& ui, float& vr, float& vi)
{
    float c0a = __cosf(a[0]), s0a = __sinf(a[0]);
    float c1a = __cosf(a[1]), s1a = __sinf(a[1]);
    float c2a = __cosf(a[2]), s2a = __sinf(a[2]);
    float c3a = __cosf(a[3]), s3a = __sinf(a[3]);
    float c4a = __cosf(a[4]), s4a = __sinf(a[4]);
    float qw = c4a * c3a, qx = -s4a * s3a, qy = c4a * s3a, qz = s4a * c3a;
    float tw = qw * c2a - qz * s2a;
    float tx = qx * c2a + qy * s2a;
    float ty = qy * c2a - qx * s2a;
    float tz = qz * c2a + qw * s2a;
    qw = tw * c1a - ty * s1a;
    qx = tx * c1a - tz * s1a;
    qy = ty * c1a + tw * s1a;
    qz = tz * c1a + tx * s1a;
    tw = qw * c0a - qz * s0a;
    tx = qx * c0a + qy * s0a;
    ty = qy * c0a - qx * s0a;
    tz = qz * c0a + qw * s0a;
    ur = tw * gA - ty * gB;
    ui = -(tz * gA + tx * gB);
    vr = tw * gB + ty * gA;
    vi = tx * gA - tz * gB;
}

// ---------------------------------------------------------------------------
// Main kernel: one thread per batch element; R9 structure with
//  (a) CRZ folded into the wire-3 apply (y = E(g) * w, w via rr-factoring)
//  (b) constant-offset angle loads under uniform window-type branches
// ---------------------------------------------------------------------------
__global__ __launch_bounds__(128, 1) void quanv_kernel(
    const float* __restrict__ crz_p, const float* __restrict__ ry_p,
    const float* __restrict__ fc1_b, const float* __restrict__ fc2_w,
    const float* __restrict__ fc2_b, float* __restrict__ out)
{
    const int b = blockIdx.x * 128 + threadIdx.x;
    const float RS = 0.7071067811865476f;

    // CRZ phases
    const float th = __ldg(crz_p);
    const float c1 = __cosf(0.5f * th), s1 = __sinf(0.5f * th);
    const float c2 = __cosf(th),        s2 = __sinf(th);
    const float c4 = __cosf(2.0f * th), s4 = __sinf(2.0f * th);

    const float ryt = __ldg(ry_p);
    const float cTH  = __cosf(ryt);
    const float s2TH = 2.0f * __sinf(ryt);
    const float chh = __cosf(0.5f * ryt), shh = __sinf(0.5f * ryt);
    const float gAf = RS * (chh + shh), gBf = RS * (chh - shh);  // H*Ry entries

    // wire-3 factoring: pick direction with |sel| = max(|gA|,|gB|)
    const bool modeA = fabsf(gAf) >= fabsf(gBf);
    const float selF = modeA ? gAf : gBf;
    const float rrF  = modeA ? (gBf / gAf) : (gAf / gBf);

    float gA = RS, gB = RS;      // step 0: plain H
    float sel = RS, rr = 1.0f;   // step 0: u=v -> rr=1 in either mode

    // State |0000>
    float Sr[16], Si[16];
    #pragma unroll
    for (int n = 0; n < 16; n++) { Sr[n] = 0.f; Si[n] = 0.f; }
    Sr[0] = 1.f;

    // Fused fc1 accumulators
    float h1[20];
    #pragma unroll
    for (int o = 0; o < 20; o++) h1[o] = __ldg(&fc1_b[o]);

    // Angles for step 0 (window (0,0), full 4x4), constant offsets
    const float* nb = g_xT + b;
    float A[16];
    #pragma unroll
    for (int k = 0; k < 16; k++)
        A[k] = nb[((k >> 2) * 28 + (k & 3)) * B_TOTAL];
    nb += 2 * B_TOTAL;           // -> window (0,1)

    int nwi = 0, nwj = 1;        // window coords of the NEXT load
    #pragma unroll 1
    for (int s = 0; s < NSTEPS; s++) {
        // ---- prefetch next step's angles: uniform window-type branches ----
        float An[16];
        if (s == NSTEPS - 1) {
            #pragma unroll
            for (int k = 0; k < 16; k++) An[k] = 0.f;
        } else if (nwj != 13 && nwi != 13) {        // full 4x4 (majority)
            #pragma unroll
            for (int k = 0; k < 16; k++)
                An[k] = nb[((k >> 2) * 28 + (k & 3)) * B_TOTAL];
        } else if (nwj == 13 && nwi == 13) {        // corner 2x2
            #pragma unroll
            for (int k = 0; k < 16; k++)
                An[k] = (k < 4) ? nb[((k >> 1) * 28 + (k & 1)) * B_TOTAL] : 0.f;
        } else if (nwj == 13) {                     // right edge 4x2
            #pragma unroll
            for (int k = 0; k < 16; k++)
                An[k] = (k < 8) ? nb[((k >> 1) * 28 + (k & 1)) * B_TOTAL] : 0.f;
        } else {                                    // bottom edge 2x4
            #pragma unroll
            for (int k = 0; k < 16; k++)
                An[k] = (k < 8) ? nb[((k >> 2) * 28 + (k & 3)) * B_TOTAL] : 0.f;
        }
        // advance base pointer (uniform)
        if (nwj == 13) { nb += 30 * B_TOTAL; nwj = 0; nwi++; }
        else           { nb += 2 * B_TOTAL;  nwj++; }

        // ---- wires 0..2: quaternion chains + applies ----
        {
            float ur, ui, vr, vi;
            chain5(A, gA, gB, ur, ui, vr, vi);
            applyUV<8>(Sr, Si, ur, ui, vr, vi);
            chain5(A + 5, gA, gB, ur, ui, vr, vi);
            applyUV<4>(Sr, Si, ur, ui, vr, vi);
            chain5(A + 10, gA, gB, ur, ui, vr, vi);
            applyUV<2>(Sr, Si, ur, ui, vr, vi);
        }

        // ---- wire 3 with CRZ folded in ----
        {
            float c0a = __cosf(A[15]), s0a = __sinf(A[15]);
            float fr = sel * c0a, fi = -sel * s0a;        // phi
            // phase products (phi * d): P1n=phi(c1,-s1), P1p=phi(c1,s1), P2n=phi(c2,-s2)
            float p1nr = fr * c1 + fi * s1, p1ni = fi * c1 - fr * s1;
            float p1pr = fr * c1 - fi * s1, p1pi = fi * c1 + fr * s1;
            float p2nr = fr * c2 + fi * s2, p2ni = fi * c2 - fr * s2;
            // K2 = conj(phi)*(c2,-s2), K4 = conj(phi)*(c4,s4)
            float k2r = fr * c2 - fi * s2, k2i = -(fr * s2 + fi * c2);
            float k4r = fr * c4 + fi * s4, k4i = fr * s4 - fi * c4;

            #define W3PAIR(G, E0R, E0I, E1R, E1I) { \
                const int i0 = 2*(G), i1 = 2*(G)+1; \
                float x0r = Sr[i0], x0i = Si[i0], x1r = Sr[i1], x1i = Si[i1]; \
                float w0r, w0i, w1r, w1i; \
                if (modeA) { \
                    w0r = fmaf(rr, x1r, x0r);  w0i = fmaf(rr, x1i, x0i); \
                    w1r = fmaf(rr, x0r, -x1r); w1i = fmaf(rr, x0i, -x1i); \
                } else { \
                    w0r = fmaf(rr, x0r, x1r);  w0i = fmaf(rr, x0i, x1i); \
                    w1r = fmaf(-rr, x1r, x0r); w1i = fmaf(-rr, x1i, x0i); \
                } \
                Sr[i0] = (E0R) * w0r - (E0I) * w0i; \
                Si[i0] = (E0R) * w0i + (E0I) * w0r; \
                Sr[i1] = (E1R) * w1r - (E1I) * w1i; \
                Si[i1] = (E1R) * w1i + (E1I) * w1r; \
            }
            // sgn table {0,-1,-1,0,-1,-2,0,1,-1,0,-2,1,0,1,1,4}
            W3PAIR(0, fr,   fi,    p1pr, -p1pi)   // d0=1,        d1=(c1,-s1)
            W3PAIR(1, p1nr, p1ni,  fr,   -fi)     // d0=(c1,-s1), d1=1
            W3PAIR(2, p1nr, p1ni,  k2r,   k2i)    // d0=(c1,-s1), d1=(c2,-s2)
            W3PAIR(3, fr,   fi,    p1nr, -p1ni)   // d0=1,        d1=(c1,s1)
            W3PAIR(4, p1nr, p1ni,  fr,   -fi)     // d0=(c1,-s1), d1=1
            W3PAIR(5, p2nr, p2ni,  p1nr, -p1ni)   // d0=(c2,-s2), d1=(c1,s1)
            W3PAIR(6, fr,   fi,    p1nr, -p1ni)   // d0=1,        d1=(c1,s1)
            W3PAIR(7, p1pr, p1pi,  k4r,   k4i)    // d0=(c1,s1),  d1=(c4,s4)
            #undef W3PAIR
        }

        // ---- probs + Z butterfly (state is post-CRZ; z's are diag-invariant)
        float p[16];
        #pragma unroll
        for (int n = 0; n < 16; n++) p[n] = Sr[n] * Sr[n] + Si[n] * Si[n];
        float t8[8], z3 = 0.f;
        #pragma unroll
        for (int g = 0; g < 8; g++) { t8[g] = p[2*g] + p[2*g+1]; z3 += p[2*g] - p[2*g+1]; }
        float t4[4], z2 = 0.f;
        #pragma unroll
        for (int g = 0; g < 4; g++) { t4[g] = t8[2*g] + t8[2*g+1]; z2 += t8[2*g] - t8[2*g+1]; }
        float t2[2], z1 = 0.f;
        #pragma unroll
        for (int g = 0; g < 2; g++) { t2[g] = t4[2*g] + t4[2*g+1]; z1 += t4[2*g] - t4[2*g+1]; }
        float z0 = t2[0] - t2[1];

        // ---- X expectations + rotated observables ----
        float x0 = xdot<8>(Sr, Si), x1 = xdot<4>(Sr, Si);
        float x2 = xdot<2>(Sr, Si), x3 = xdot<1>(Sr, Si);
        float ev[4];
        ev[0] = cTH * z0 - s2TH * x0;
        ev[1] = cTH * z1 - s2TH * x1;
        ev[2] = cTH * z2 - s2TH * x2;
        ev[3] = cTH * z3 - s2TH * x3;

        // ---- fused fc1 ----
        {
            const float4* w4 = (const float4*)(g_w1T + s * 80);
            #pragma unroll
            for (int w = 0; w < 4; w++) {
                #pragma unroll
                for (int q = 0; q < 5; q++) {
                    float4 ww = __ldg(&w4[w * 5 + q]);
                    h1[q * 4 + 0] += ev[w] * ww.x;
                    h1[q * 4 + 1] += ev[w] * ww.y;
                    h1[q * 4 + 2] += ev[w] * ww.z;
                    h1[q * 4 + 3] += ev[w] * ww.w;
                }
            }
        }

        // rotate prefetched angles in; switch G (and wire-3 consts) after step 0
        #pragma unroll
        for (int k = 0; k < 16; k++) A[k] = An[k];
        gA = gAf; gB = gBf; sel = selF; rr = rrF;
    }

    // ---- leaky relu + fc2 ----
    float o0 = __ldg(&fc2_b[0]), o1 = __ldg(&fc2_b[1]);
    #pragma unroll
    for (int o = 0; o < 20; o++) {
        float hv = h1[o];
        hv = (hv > 0.f) ? hv : 0.1f * hv;
        o0 += hv * __ldg(&fc2_w[o]);
        o1 += hv * __ldg(&fc2_w[20 + o]);
    }
    out[b * 2 + 0] = o0;
    out[b * 2 + 1] = o1;
}

// ---------------------------------------------------------------------------
// Launch
// ---------------------------------------------------------------------------
extern "C" void kernel_launch(void* const* d_in, const int* in_sizes, int n_in,
                              void* d_out, int out_size) {
    const float* x      = (const float*)d_in[0];
    const float* crz_t  = (const float*)d_in[1];
    const float* ry_t   = (const float*)d_in[2];
    const float* fc1_w  = (const float*)d_in[3];
    const float* fc1_b  = (const float*)d_in[4];
    const float* fc2_w  = (const float*)d_in[5];
    const float* fc2_b  = (const float*)d_in[6];
    float* out = (float*)d_out;

    dim3 tbP(8, 32);
    dim3 tgP(B_TOTAL / 32, 26);
    prep_kernel<<<tgP, tbP>>>(x, fc1_w);

    quanv_kernel<<<B_TOTAL / 128, 128>>>(crz_t, ry_t, fc1_b, fc2_w, fc2_b, out);
}